// round 5
// baseline (speedup 1.0000x reference)
#include <cuda_runtime.h>
#include <cuda_bf16.h>
#include <cstdint>

// ---------------------------------------------------------------------------
// Problem dims (fixed by the dataset)
#define M_TOT 8192   // B*S = 4*2048
#define K_TOT 4096
#define N_TOT 4096

// GEMM tiling (int8, m16n8k32)
#define BM 128
#define BN 128
#define BK 64          // K bytes per stage
#define STAGES 4
#define NKT (K_TOT / BK)   // 64
#define THREADS 256

// smem tile: 128 rows x (64B data + 16B pad) = 80B rows, ldmatrix conflict-free
#define ROW_B 80
#define TILE_BYTES (128 * ROW_B)          // 10240
#define STAGE_BYTES (2 * TILE_BYTES)      // 20480
#define SMEM_TOTAL (STAGES * STAGE_BYTES) // 81920

// Scratch: quantized-centered activations (s8), packed weights (u8), row sums.
__device__ __align__(16) int8_t  g_Xq[(size_t)M_TOT * K_TOT];
__device__ __align__(16) uint8_t g_Wp[(size_t)N_TOT * K_TOT];
__device__ float g_S[M_TOT];

// ---------------------------------------------------------------------------
// Kernel 1: quantize activations -> s8, and per-row sums S[m].
// One block per row (4096 elems = 1024 float4; 256 threads x 4 iters).
// ---------------------------------------------------------------------------
__global__ void __launch_bounds__(256) quant_x_kernel(
    const float* __restrict__ x,
    const float* __restrict__ act_scale,
    const int* __restrict__ act_zp) {
    const int m = blockIdx.x;
    const int tid = threadIdx.x;
    const float inv_s = 1.0f / act_scale[0];
    const float zp = (float)act_zp[0];
    const float lo = 0.0f - zp, hi = 255.0f - zp;

    const float4* xrow = (const float4*)(x + (size_t)m * K_TOT);
    int* orow = (int*)(g_Xq + (size_t)m * K_TOT);

    float sum = 0.0f;
    #pragma unroll
    for (int it = 0; it < 4; it++) {
        const int idx = it * 256 + tid;
        float4 v = xrow[idx];
        float q0 = fminf(fmaxf(rintf(v.x * inv_s), lo), hi);
        float q1 = fminf(fmaxf(rintf(v.y * inv_s), lo), hi);
        float q2 = fminf(fmaxf(rintf(v.z * inv_s), lo), hi);
        float q3 = fminf(fmaxf(rintf(v.w * inv_s), lo), hi);
        sum += q0 + q1 + q2 + q3;
        int i0 = (int)q0, i1 = (int)q1, i2 = (int)q2, i3 = (int)q3;
        unsigned p = (unsigned)(i0 & 0xFF) | ((unsigned)(i1 & 0xFF) << 8) |
                     ((unsigned)(i2 & 0xFF) << 16) | ((unsigned)(i3 & 0xFF) << 24);
        orow[idx] = (int)p;
    }

    // block reduce sum
    __shared__ float red[8];
    #pragma unroll
    for (int o = 16; o > 0; o >>= 1)
        sum += __shfl_down_sync(0xFFFFFFFFu, sum, o);
    if ((tid & 31) == 0) red[tid >> 5] = sum;
    __syncthreads();
    if (tid < 8) {
        float s = red[tid];
        #pragma unroll
        for (int o = 4; o > 0; o >>= 1)
            s += __shfl_down_sync(0xFFu, s, o);
        if (tid == 0) g_S[m] = s;
    }
}

// ---------------------------------------------------------------------------
// Kernel 2: pack weights int32 -> u8. One int4 (4 values) -> one u32.
// ---------------------------------------------------------------------------
__global__ void __launch_bounds__(256) conv_w_kernel(const int* __restrict__ wq) {
    size_t idx = (size_t)blockIdx.x * blockDim.x + threadIdx.x;
    int4 v = ((const int4*)wq)[idx];
    unsigned p = (unsigned)(v.x & 0xFF) | ((unsigned)(v.y & 0xFF) << 8) |
                 ((unsigned)(v.z & 0xFF) << 16) | ((unsigned)(v.w & 0xFF) << 24);
    ((unsigned*)g_Wp)[idx] = p;
}

// ---------------------------------------------------------------------------
// Kernel 3: int8 GEMM. acc[m,o] = dot(xc_s8[m,:], wq_u8[o,:]) in s32.
// out = (sa*ws[o])*acc - (sa*ws[o]*wzp[o])*S[m] + bias[o]
// 128x128 tile, BK=64, 4-stage cp.async, mma.sync.m16n8k32.s32.s8.u8.s32.
// 8 warps: 2(M) x 4(N); warp tile 64x32.
// ---------------------------------------------------------------------------
__global__ void __launch_bounds__(THREADS, 2)
gemm_kernel(const float* __restrict__ ws,
            const int* __restrict__ wzp,
            const float* __restrict__ bias,
            const float* __restrict__ act_scale,
            float* __restrict__ out) {
    extern __shared__ char smem[];
    const uint32_t smem_base = (uint32_t)__cvta_generic_to_shared(smem);

    const int tid    = threadIdx.x;
    const int lane   = tid & 31;
    const int wid    = tid >> 5;
    const int warp_m = wid & 1;
    const int warp_n = wid >> 1;
    const int bm = blockIdx.y;
    const int bn = blockIdx.x;

    const int8_t*  Ag = g_Xq + (size_t)bm * BM * K_TOT;
    const uint8_t* Bg = g_Wp + (size_t)bn * BN * K_TOT;

    // cp.async: tile = 128 rows x 4 x 16B chunks = 512 chunks; 256 thr x 2
    const int ld_row0 = tid >> 2;   // 0..63
    const int ld_col  = tid & 3;    // 16B chunk within row

    // ldmatrix offsets (A: 16x32B quads; B: same structure)
    const uint32_t aoff = (uint32_t)(warp_m * 64 + (lane & 15)) * ROW_B
                        + ((lane >> 4) * 16);
    const uint32_t boff = (uint32_t)(warp_n * 32 + (lane & 7) + ((lane >> 4) << 3)) * ROW_B
                        + (((lane >> 3) & 1) * 16);

    int acc[4][4][4];
    #pragma unroll
    for (int i = 0; i < 4; i++)
        #pragma unroll
        for (int j = 0; j < 4; j++)
            #pragma unroll
            for (int k = 0; k < 4; k++) acc[i][j][k] = 0;

    auto load_stage = [&](int stage, int kt) {
        const uint32_t sa = smem_base + stage * STAGE_BYTES;
        const uint32_t sb = sa + TILE_BYTES;
        const int k0 = kt * BK;
        #pragma unroll
        for (int i = 0; i < 2; i++) {
            const int row = ld_row0 + i * 64;
            const uint32_t soff = (uint32_t)row * ROW_B + ld_col * 16;
            asm volatile("cp.async.cg.shared.global [%0], [%1], 16;\n"
                         :: "r"(sa + soff),
                            "l"(Ag + (size_t)row * K_TOT + k0 + ld_col * 16));
            asm volatile("cp.async.cg.shared.global [%0], [%1], 16;\n"
                         :: "r"(sb + soff),
                            "l"(Bg + (size_t)row * K_TOT + k0 + ld_col * 16));
        }
    };

    #pragma unroll
    for (int s = 0; s < STAGES - 1; s++) {
        load_stage(s, s);
        asm volatile("cp.async.commit_group;\n");
    }
    asm volatile("cp.async.wait_group %0;\n" :: "n"(STAGES - 2));
    __syncthreads();

    for (int kt = 0; kt < NKT; kt++) {
        const int stage = kt & (STAGES - 1);
        const uint32_t sa = smem_base + stage * STAGE_BYTES;
        const uint32_t sb = sa + TILE_BYTES;

        #pragma unroll
        for (int k32 = 0; k32 < 2; k32++) {   // two k=32 steps per 64B stage
            uint32_t a[4][4], b[2][4];
            #pragma unroll
            for (int mi = 0; mi < 4; mi++) {
                const uint32_t addr = sa + aoff + mi * (16 * ROW_B) + k32 * 32;
                asm volatile(
                    "ldmatrix.sync.aligned.m8n8.x4.shared.b16 {%0,%1,%2,%3}, [%4];\n"
                    : "=r"(a[mi][0]), "=r"(a[mi][1]), "=r"(a[mi][2]), "=r"(a[mi][3])
                    : "r"(addr));
            }
            #pragma unroll
            for (int nj = 0; nj < 2; nj++) {
                const uint32_t addr = sb + boff + nj * (16 * ROW_B) + k32 * 32;
                asm volatile(
                    "ldmatrix.sync.aligned.m8n8.x4.shared.b16 {%0,%1,%2,%3}, [%4];\n"
                    : "=r"(b[nj][0]), "=r"(b[nj][1]), "=r"(b[nj][2]), "=r"(b[nj][3])
                    : "r"(addr));
            }
            #pragma unroll
            for (int mi = 0; mi < 4; mi++) {
                #pragma unroll
                for (int ni = 0; ni < 4; ni++) {
                    const uint32_t b0 = b[ni >> 1][(ni & 1) * 2 + 0];
                    const uint32_t b1 = b[ni >> 1][(ni & 1) * 2 + 1];
                    int* c = acc[mi][ni];
                    asm volatile(
                        "mma.sync.aligned.m16n8k32.row.col.s32.s8.u8.s32 "
                        "{%0,%1,%2,%3}, {%4,%5,%6,%7}, {%8,%9}, {%0,%1,%2,%3};\n"
                        : "+r"(c[0]), "+r"(c[1]), "+r"(c[2]), "+r"(c[3])
                        : "r"(a[mi][0]), "r"(a[mi][1]), "r"(a[mi][2]), "r"(a[mi][3]),
                          "r"(b0), "r"(b1));
                }
            }
        }

        const int nkt = kt + STAGES - 1;
        if (nkt < NKT) load_stage(nkt & (STAGES - 1), nkt);
        asm volatile("cp.async.commit_group;\n");
        asm volatile("cp.async.wait_group %0;\n" :: "n"(STAGES - 2));
        __syncthreads();
    }

    // Epilogue: out = sc*acc - (sc*wzp)*S[m] + bias
    const float sa_s = act_scale[0];
    const int row_base = bm * BM + warp_m * 64;
    const int col_base = bn * BN + warp_n * 32;
    #pragma unroll
    for (int ni = 0; ni < 4; ni++) {
        const int col = col_base + ni * 8 + (lane & 3) * 2;
        const float2 wsv = *(const float2*)(ws + col);
        const float2 bv  = *(const float2*)(bias + col);
        const int2   zpv = *(const int2*)(wzp + col);
        const float s0 = sa_s * wsv.x;
        const float s1 = sa_s * wsv.y;
        const float t0 = s0 * (float)zpv.x;
        const float t1 = s1 * (float)zpv.y;
        #pragma unroll
        for (int mi = 0; mi < 4; mi++) {
            const int r0 = row_base + mi * 16 + (lane >> 2);
            const float S0 = g_S[r0];
            const float S1 = g_S[r0 + 8];
            const int* c = acc[mi][ni];
            float2 o0, o1;
            o0.x = (float)c[0] * s0 - t0 * S0 + bv.x;
            o0.y = (float)c[1] * s1 - t1 * S0 + bv.y;
            o1.x = (float)c[2] * s0 - t0 * S1 + bv.x;
            o1.y = (float)c[3] * s1 - t1 * S1 + bv.y;
            *(float2*)(out + (size_t)r0 * N_TOT + col) = o0;
            *(float2*)(out + (size_t)(r0 + 8) * N_TOT + col) = o1;
        }
    }
}

// ---------------------------------------------------------------------------
// Launch. Inputs: x, weight_q, weight_scales, weight_zero_points,
// act_scales, act_zero_points, bias. Output: float32 [8192, 4096].
// ---------------------------------------------------------------------------
extern "C" void kernel_launch(void* const* d_in, const int* in_sizes, int n_in,
                              void* d_out, int out_size) {
    const float* x    = (const float*)d_in[0];
    const int*   wq   = (const int*)d_in[1];
    const float* wsc  = (const float*)d_in[2];
    const int*   wzp  = (const int*)d_in[3];
    const float* asc  = (const float*)d_in[4];
    const int*   azp  = (const int*)d_in[5];
    const float* bias = (const float*)d_in[6];
    float* out = (float*)d_out;

    quant_x_kernel<<<M_TOT, 256>>>(x, asc, azp);

    {
        const size_t n4 = (size_t)N_TOT * K_TOT / 4;
        conv_w_kernel<<<(unsigned)(n4 / 256), 256>>>(wq);
    }
    {
        cudaFuncSetAttribute(gemm_kernel,
                             cudaFuncAttributeMaxDynamicSharedMemorySize,
                             SMEM_TOTAL);
        dim3 grid(N_TOT / BN, M_TOT / BM);  // (32, 64)
        gemm_kernel<<<grid, THREADS, SMEM_TOTAL>>>(wsc, wzp, bias, asc, out);
    }
}